// round 15
// baseline (speedup 1.0000x reference)
#include <cuda_runtime.h>
#include <cuda_fp16.h>
#include <math.h>
#include <stdint.h>

#define Bb    64
#define Tt    2048
#define ENC   512
#define DEC   1024
#define CONVC 32
#define KW    31
#define HID   256
#define PADW  15

#define KSTEPS 36             // 16-col sub-steps in packed B (incl. zero pad)
#define NSEG   32

// ---------------- device scratch ----------------
__device__ float  g_dbc[Bb * HID];                // dec@Wdec^T + b_enc
__device__ uint4  g_Bp4[KSTEPS * 512];            // fp16 weights, paired n8 tiles
__device__ float  g_energy[Bb * Tt];
__device__ float  g_part[NSEG * Bb * ENC];
__device__ float  g_stat[2 * Bb];                 // {M, 1/sum} per batch
__device__ __half g_encH[(size_t)Bb * Tt * ENC];  // fp16 enc cache (128 MiB)

// ---------------- helpers ----------------
__device__ __forceinline__ uint32_t packh(float x, float y) {
    __half2 h = __floats2half2_rn(x, y);
    return *(uint32_t*)&h;
}
__device__ __forceinline__ uint32_t smem_u32(const void* p) {
    uint32_t a;
    asm("{ .reg .u64 t; cvta.to.shared.u64 t, %1; cvt.u32.u64 %0, t; }" : "=r"(a) : "l"(p));
    return a;
}
__device__ __forceinline__ void mma16816(float* d, const uint32_t* a,
                                         uint32_t b0, uint32_t b1) {
    asm volatile(
        "mma.sync.aligned.m16n8k16.row.col.f32.f16.f16.f32 "
        "{%0,%1,%2,%3}, {%4,%5,%6,%7}, {%8,%9}, {%0,%1,%2,%3};"
        : "+f"(d[0]), "+f"(d[1]), "+f"(d[2]), "+f"(d[3])
        : "r"(a[0]), "r"(a[1]), "r"(a[2]), "r"(a[3]), "r"(b0), "r"(b1));
}
__device__ __forceinline__ void cp_async16(uint32_t dst, const void* src) {
    asm volatile("cp.async.ca.shared.global [%0], [%1], 16;" :: "r"(dst), "l"(src));
}
#define CP_COMMIT() asm volatile("cp.async.commit_group;" ::: "memory")
#define CP_WAIT0()  asm volatile("cp.async.wait_group 0;" ::: "memory")
#define LDMAT(r, ad)                                                              \
    asm volatile("ldmatrix.sync.aligned.m8n8.x4.shared.b16 {%0,%1,%2,%3}, [%4];"  \
        : "=r"((r)[0]), "=r"((r)[1]), "=r"((r)[2]), "=r"((r)[3]) : "r"(ad))

// ============================================================
// prep: (blocks 0..63) dbc; (blocks 64..135) pack Wext fragments
// ============================================================
__device__ __forceinline__ float wval(const float* Wenc, const float* Watt,
                                      const float* convw, int h, int col) {
    if (col < ENC) return Wenc[(size_t)h * ENC + col];
    int cc = col - ENC;
    if (cc < KW) {
        float s = 0.f;
        #pragma unroll
        for (int c = 0; c < CONVC; c++) s += Watt[h * CONVC + c] * convw[c * KW + cc];
        return s;
    }
    return 0.f;
}

__global__ void prep_kernel(const float* __restrict__ dec_state,
                            const float* __restrict__ Wdec,
                            const float* __restrict__ benc,
                            const float* __restrict__ Wenc,
                            const float* __restrict__ Watt,
                            const float* __restrict__ convw) {
    if (blockIdx.x < Bb) {
        int b = blockIdx.x;
        int warp = threadIdx.x >> 5, lane = threadIdx.x & 31;
        for (int h = warp; h < HID; h += 8) {
            float s = 0.f;
            const float* xr = dec_state + (size_t)b * DEC;
            const float* wr = Wdec + (size_t)h * DEC;
            for (int c = lane * 4; c < DEC; c += 32 * 4) {
                float4 x = *(const float4*)&xr[c];
                float4 w = *(const float4*)&wr[c];
                s += x.x * w.x + x.y * w.y + x.z * w.z + x.w * w.w;
            }
            #pragma unroll
            for (int off = 16; off > 0; off >>= 1) s += __shfl_xor_sync(0xFFFFFFFFu, s, off);
            if (lane == 0) g_dbc[b * HID + h] = s + benc[h];
        }
    } else {
        int idx = (blockIdx.x - Bb) * 256 + threadIdx.x;
        if (idx >= KSTEPS * 512) return;
        int lane = idx & 31, pg = (idx >> 5) & 15, s = idx >> 9;
        int jj0 = (pg >> 2) * 8 + (pg & 3) * 2;
        int h0 = jj0 * 8 + (lane >> 2);
        int h1 = h0 + 8;
        int k = s * 16 + (lane & 3) * 2;
        uint4 r;
        r.x = packh(wval(Wenc, Watt, convw, h0, k),     wval(Wenc, Watt, convw, h0, k + 1));
        r.y = packh(wval(Wenc, Watt, convw, h0, k + 8), wval(Wenc, Watt, convw, h0, k + 9));
        r.z = packh(wval(Wenc, Watt, convw, h1, k),     wval(Wenc, Watt, convw, h1, k + 1));
        r.w = packh(wval(Wenc, Watt, convw, h1, k + 8), wval(Wenc, Watt, convw, h1, k + 9));
        g_Bp4[idx] = r;
    }
}

// ============================================================
// energy kernel: CTA = 64 t x 256 h; 8 warps (2 M x 4 N)
// K=64 fused steps: 8 full + 1 half (conv) -> 9 barriers
// Also writes fp16 enc tiles to g_encH (consumed by attc_part).
// ============================================================
#define ASTRIDE 72   // halves per row (144B) -> conflict-free ldmatrix
#define A_BUF_HALVES (64 * ASTRIDE)
#define DSMEM_A  (2 * A_BUF_HALVES * 2)        // 18432 B
#define DSMEM_SZ (DSMEM_A + 2 * 32768)         // + B stages = 83968 B

__global__ __launch_bounds__(256, 2)
void energy_kernel(const float* __restrict__ enc,
                   const float* __restrict__ prev,
                   const float* __restrict__ ww,
                   const float* __restrict__ wb) {
    extern __shared__ __align__(16) char dyn[];
    __half* aS = (__half*)dyn;                      // [2][64*ASTRIDE]
    const uint32_t bBase = smem_u32(dyn + DSMEM_A); // B stages: 2 x 32KB
    uint4* bS = (uint4*)(dyn + DSMEM_A);

    __shared__ float wwS[HID], dbS[HID];
    __shared__ float redS[64][5];

    const int tid = threadIdx.x;
    const int b = blockIdx.y, t0 = blockIdx.x * 64;
    const int warp = tid >> 5, lane = tid & 31;
    const int warp_m = warp >> 2, warp_n = warp & 3;
    const int g = lane >> 2, tq = lane & 3;

    if (tid < HID) {
        wwS[tid] = ww[tid];
        dbS[tid] = g_dbc[b * HID + tid];
    }

    float d[2][8][4];
    #pragma unroll
    for (int mi = 0; mi < 2; mi++)
        #pragma unroll
        for (int jj = 0; jj < 8; jj++)
            #pragma unroll
            for (int q = 0; q < 4; q++) d[mi][jj][q] = 0.f;

    const float* encB = enc + (size_t)b * Tt * ENC;
    const float* prevB = prev + b * Tt;

    // staging: row = tid>>2 (0..63), cols (tid&3)*16 .. +15
    const int srow = tid >> 2, sc0 = (tid & 3) * 16;
    __half* gHrow = g_encH + ((size_t)b * Tt + t0 + srow) * ENC + sc0;

    // ldmatrix base addresses: [buf][mi]; kh adds kh*32 bytes
    const int lm = lane >> 3, lr = lane & 7;
    const int arow0 = warp_m * 32 + (lm & 1) * 8 + lr;
    const int acol = (lm >> 1) * 8;
    const uint32_t la00 = smem_u32(&aS[(arow0 +  0) * ASTRIDE + acol]);
    const uint32_t la01 = smem_u32(&aS[(arow0 + 16) * ASTRIDE + acol]);
    const uint32_t la10 = la00 + A_BUF_HALVES * 2;
    const uint32_t la11 = la01 + A_BUF_HALVES * 2;

    // ---- prologue: B stage 0 (32KB); A step 0 in regs ----
    {
        uint32_t dst = bBase + tid * 16;
        #pragma unroll
        for (int q = 0; q < 8; q++)
            cp_async16(dst + q * 4096, &g_Bp4[q * 256 + tid]);
        CP_COMMIT();
    }
    float4 pA, pB, pC, pD;
    pA = *(const float4*)&encB[(size_t)(t0 + srow) * ENC + sc0];
    pB = *(const float4*)&encB[(size_t)(t0 + srow) * ENC + sc0 + 4];
    pC = *(const float4*)&encB[(size_t)(t0 + srow) * ENC + sc0 + 8];
    pD = *(const float4*)&encB[(size_t)(t0 + srow) * ENC + sc0 + 12];

    // PF: 0 = enc prefetch + full B, 2 = none (tail)
#define FSTEP(S, BUF, LM0, LM1, PF, NKH) do {                                     \
    {                                                                             \
        uint32_t sb_ = (BUF) * A_BUF_HALVES;                                      \
        uint4 u0, u1;                                                             \
        u0.x = packh(pA.x, pA.y); u0.y = packh(pA.z, pA.w);                       \
        u0.z = packh(pB.x, pB.y); u0.w = packh(pB.z, pB.w);                       \
        u1.x = packh(pC.x, pC.y); u1.y = packh(pC.z, pC.w);                       \
        u1.z = packh(pD.x, pD.y); u1.w = packh(pD.z, pD.w);                       \
        *(uint4*)&aS[sb_ + srow * ASTRIDE + sc0]     = u0;                        \
        *(uint4*)&aS[sb_ + srow * ASTRIDE + sc0 + 8] = u1;                        \
        if ((S) < 8) {                                                            \
            *(uint4*)&gHrow[(S) * 64]     = u0;                                   \
            *(uint4*)&gHrow[(S) * 64 + 8] = u1;                                   \
        }                                                                         \
    }                                                                             \
    CP_WAIT0();                                                                   \
    __syncthreads();                                                              \
    if (PF == 0) {                                                                \
        const int _sn = (S) + 1;                                                  \
        uint32_t _bd = bBase + ((_sn) & 1) * 32768 + tid * 16;                    \
        const int _nq = (_sn < 8) ? 8 : 4;                                        \
        for (int q = 0; q < _nq; q++)                                             \
            cp_async16(_bd + q * 4096, &g_Bp4[_sn * 2048 + q * 256 + tid]);       \
        CP_COMMIT();                                                              \
        if (_sn < 8) {                                                            \
            const float* _r = &encB[(size_t)(t0 + srow) * ENC + _sn * 64 + sc0];  \
            pA = *(const float4*)&_r[0];  pB = *(const float4*)&_r[4];            \
            pC = *(const float4*)&_r[8];  pD = *(const float4*)&_r[12];           \
        } else {                                                                  \
            float _v[16];                                                         \
            _Pragma("unroll")                                                     \
            for (int i = 0; i < 16; i++) {                                        \
                int cc = sc0 + i;                                                 \
                float x = 0.f;                                                    \
                if (cc < KW) {                                                    \
                    int src = t0 + srow + cc - PADW;                              \
                    if (src >= 0 && src < Tt) x = prevB[src];                     \
                }                                                                 \
                _v[i] = x;                                                        \
            }                                                                     \
            pA.x=_v[0]; pA.y=_v[1]; pA.z=_v[2]; pA.w=_v[3];                       \
            pB.x=_v[4]; pB.y=_v[5]; pB.z=_v[6]; pB.w=_v[7];                       \
            pC.x=_v[8]; pC.y=_v[9]; pC.z=_v[10]; pC.w=_v[11];                     \
            pD.x=_v[12]; pD.y=_v[13]; pD.z=_v[14]; pD.w=_v[15];                   \
        }                                                                         \
    }                                                                             \
    _Pragma("unroll")                                                             \
    for (int kh = 0; kh < (NKH); kh++) {                                          \
        uint32_t a0[4], a1[4];                                                    \
        LDMAT(a0, (LM0) + kh * 32);                                               \
        LDMAT(a1, (LM1) + kh * 32);                                               \
        _Pragma("unroll")                                                         \
        for (int p = 0; p < 4; p++) {                                             \
            uint4 B2 = bS[(BUF) * 2048 + kh * 512 + (warp_n * 4 + p) * 32 + lane];\
            mma16816(d[0][p * 2 + 0], a0, B2.x, B2.y);                            \
            mma16816(d[0][p * 2 + 1], a0, B2.z, B2.w);                            \
            mma16816(d[1][p * 2 + 0], a1, B2.x, B2.y);                            \
            mma16816(d[1][p * 2 + 1], a1, B2.z, B2.w);                            \
        }                                                                         \
    }                                                                             \
} while (0)

    for (int s = 0; s < 8; s += 2) {
        FSTEP(s,     0, la00, la01, 0, 4);
        FSTEP(s + 1, 1, la10, la11, 0, 4);
    }
    FSTEP(8, 0, la00, la01, 2, 2);   // conv tail: K=32
#undef FSTEP

    // ---- epilogue: e(row) = sum_h ww[h]*tanh(C + dbc[h]) ----
    float ww0[8], ww1[8], db0[8], db1[8];
    #pragma unroll
    for (int jj = 0; jj < 8; jj++) {
        int h = warp_n * 64 + jj * 8 + tq * 2;
        ww0[jj] = wwS[h];     ww1[jj] = wwS[h + 1];
        db0[jj] = dbS[h];     db1[jj] = dbS[h + 1];
    }
    #pragma unroll
    for (int mi = 0; mi < 2; mi++) {
        #pragma unroll
        for (int half = 0; half < 2; half++) {
            float e = 0.f;
            #pragma unroll
            for (int jj = 0; jj < 8; jj++) {
                e += ww0[jj] * tanhf(d[mi][jj][half * 2 + 0] + db0[jj]);
                e += ww1[jj] * tanhf(d[mi][jj][half * 2 + 1] + db1[jj]);
            }
            e += __shfl_xor_sync(0xFFFFFFFFu, e, 1);
            e += __shfl_xor_sync(0xFFFFFFFFu, e, 2);
            if (tq == 0)
                redS[warp_m * 32 + mi * 16 + half * 8 + g][warp_n] = e;
        }
    }
    __syncthreads();
    if (tid < 64) {
        float e = redS[tid][0] + redS[tid][1] + redS[tid][2] + redS[tid][3];
        g_energy[b * Tt + t0 + tid] = e + wb[0];
    }
}

// ============================================================
// softmax stats: per-b masked max + 1/sum (no att_w pass)
// ============================================================
__global__ void softmax_stats_kernel(const int* __restrict__ text_len) {
    const int b = blockIdx.x;
    const int tid = threadIdx.x;  // 512
    const int len = text_len[b];
    __shared__ float sh[512];

    float m = -3.402823466e+38f;
    for (int t = tid; t < Tt; t += 512)
        if (t < len) m = fmaxf(m, g_energy[b * Tt + t]);
    sh[tid] = m; __syncthreads();
    for (int s = 256; s > 0; s >>= 1) {
        if (tid < s) sh[tid] = fmaxf(sh[tid], sh[tid + s]);
        __syncthreads();
    }
    const float M = sh[0];
    __syncthreads();

    float sum = 0.f;
    for (int t = tid; t < Tt; t += 512)
        if (t < len) sum += __expf(g_energy[b * Tt + t] - M);
    sh[tid] = sum; __syncthreads();
    for (int s = 256; s > 0; s >>= 1) {
        if (tid < s) sh[tid] += sh[tid + s];
        __syncthreads();
    }
    if (tid == 0) {
        g_stat[2 * b]     = M;
        g_stat[2 * b + 1] = 1.f / sh[0];
    }
}

// ============================================================
// att_c partials from fp16 enc cache; also writes att_w
// ============================================================
__global__ void attc_part_kernel(const int* __restrict__ text_len,
                                 float* __restrict__ out_w) {
    const int b = blockIdx.y, seg = blockIdx.x;
    const int c4 = threadIdx.x;  // 128 threads, 4 cols each
    const int tstart = seg * (Tt / NSEG);
    __shared__ float wS[Tt / NSEG];

    if (c4 < Tt / NSEG) {
        const int t = tstart + c4;
        const int len = text_len[b];
        const float M = g_stat[2 * b], invS = g_stat[2 * b + 1];
        float w = (t < len) ? __expf(g_energy[b * Tt + t] - M) * invS : 0.f;
        wS[c4] = w;
        out_w[b * Tt + t] = w;
    }
    __syncthreads();

    float4 s = {0.f, 0.f, 0.f, 0.f};
    const __half* eh = g_encH + ((size_t)b * Tt + tstart) * ENC + c4 * 4;
    #pragma unroll 4
    for (int i = 0; i < Tt / NSEG; i++) {
        float w = wS[i];
        uint2 u = *(const uint2*)(eh + (size_t)i * ENC);
        float2 v0 = __half22float2(*(__half2*)&u.x);
        float2 v1 = __half22float2(*(__half2*)&u.y);
        s.x = fmaf(v0.x, w, s.x);
        s.y = fmaf(v0.y, w, s.y);
        s.z = fmaf(v1.x, w, s.z);
        s.w = fmaf(v1.y, w, s.w);
    }
    *(float4*)&g_part[(seg * Bb + b) * ENC + c4 * 4] = s;
}

__global__ void attc_reduce_kernel(float* __restrict__ out_c) {
    const int b = blockIdx.x;
    const int c = threadIdx.x;  // 512
    float s = 0.f;
    #pragma unroll
    for (int seg = 0; seg < NSEG; seg++)
        s += g_part[(seg * Bb + b) * ENC + c];
    out_c[b * ENC + c] = s;
}

// ============================================================
extern "C" void kernel_launch(void* const* d_in, const int* in_sizes, int n_in,
                              void* d_out, int out_size) {
    const float* enc       = (const float*)d_in[0];   // (B,T,ENC)
    const float* dec_state = (const float*)d_in[1];   // (B,DEC)
    const float* prev      = (const float*)d_in[2];   // (B,T)
    const int*   text_len  = (const int*)  d_in[3];   // (B,)
    const float* Wenc      = (const float*)d_in[4];   // (HID,ENC)
    const float* benc      = (const float*)d_in[5];   // (HID,)
    const float* Wdec      = (const float*)d_in[6];   // (HID,DEC)
    const float* Watt      = (const float*)d_in[7];   // (HID,CONV)
    const float* convw     = (const float*)d_in[8];   // (CONV,1,K)
    const float* ww        = (const float*)d_in[9];   // (1,HID)
    const float* wb        = (const float*)d_in[10];  // (1,)

    float* out   = (float*)d_out;
    float* out_c = out;                 // att_c: (B,ENC)
    float* out_w = out + Bb * ENC;      // att_w: (B,T)

    cudaFuncSetAttribute(energy_kernel, cudaFuncAttributeMaxDynamicSharedMemorySize, DSMEM_SZ);

    prep_kernel<<<Bb + (KSTEPS * 512 + 255) / 256, 256>>>(dec_state, Wdec, benc,
                                                          Wenc, Watt, convw);
    energy_kernel<<<dim3(Tt / 64, Bb), 256, DSMEM_SZ>>>(enc, prev, ww, wb);
    softmax_stats_kernel<<<Bb, 512>>>(text_len);
    attc_part_kernel<<<dim3(NSEG, Bb), 128>>>(text_len, out_w);
    attc_reduce_kernel<<<Bb, ENC>>>(out_c);
}

// round 16
// speedup vs baseline: 1.1026x; 1.1026x over previous
#include <cuda_runtime.h>
#include <cuda_fp16.h>
#include <math.h>
#include <stdint.h>

#define Bb    64
#define Tt    2048
#define ENC   512
#define DEC   1024
#define CONVC 32
#define KW    31
#define HID   256
#define PADW  15

#define KSTEPS 36             // 16-col sub-steps in packed B (incl. zero pad)
#define NSEG   32

// ---------------- device scratch ----------------
__device__ float  g_dbc[Bb * HID];                // dec@Wdec^T + b_enc
__device__ uint4  g_Bp4[KSTEPS * 512];            // fp16 weights, paired n8 tiles
__device__ float  g_energy[Bb * Tt];
__device__ float  g_part[NSEG * Bb * ENC];
__device__ float  g_stat[2 * Bb];                 // {M, 1/sum} per batch
__device__ __half g_encH[(size_t)Bb * Tt * ENC];  // fp16 enc cache (128 MiB)

// ---------------- helpers ----------------
__device__ __forceinline__ uint32_t packh(float x, float y) {
    __half2 h = __floats2half2_rn(x, y);
    return *(uint32_t*)&h;
}
__device__ __forceinline__ uint32_t smem_u32(const void* p) {
    uint32_t a;
    asm("{ .reg .u64 t; cvta.to.shared.u64 t, %1; cvt.u32.u64 %0, t; }" : "=r"(a) : "l"(p));
    return a;
}
__device__ __forceinline__ void mma16816(float* d, const uint32_t* a,
                                         uint32_t b0, uint32_t b1) {
    asm volatile(
        "mma.sync.aligned.m16n8k16.row.col.f32.f16.f16.f32 "
        "{%0,%1,%2,%3}, {%4,%5,%6,%7}, {%8,%9}, {%0,%1,%2,%3};"
        : "+f"(d[0]), "+f"(d[1]), "+f"(d[2]), "+f"(d[3])
        : "r"(a[0]), "r"(a[1]), "r"(a[2]), "r"(a[3]), "r"(b0), "r"(b1));
}
__device__ __forceinline__ void cp_async16(uint32_t dst, const void* src) {
    asm volatile("cp.async.ca.shared.global [%0], [%1], 16;" :: "r"(dst), "l"(src));
}
#define CP_COMMIT() asm volatile("cp.async.commit_group;" ::: "memory")
#define CP_WAIT0()  asm volatile("cp.async.wait_group 0;" ::: "memory")
#define LDMAT(r, ad)                                                              \
    asm volatile("ldmatrix.sync.aligned.m8n8.x4.shared.b16 {%0,%1,%2,%3}, [%4];"  \
        : "=r"((r)[0]), "=r"((r)[1]), "=r"((r)[2]), "=r"((r)[3]) : "r"(ad))

// streaming (evict-first) global accessors
__device__ __forceinline__ void stcs4(uint4* p, uint4 v) {
    asm volatile("st.global.cs.v4.u32 [%0], {%1,%2,%3,%4};"
                 :: "l"(p), "r"(v.x), "r"(v.y), "r"(v.z), "r"(v.w) : "memory");
}
__device__ __forceinline__ float4 ldcs4f(const float4* p) {
    float4 v;
    asm volatile("ld.global.cs.v4.f32 {%0,%1,%2,%3}, [%4];"
                 : "=f"(v.x), "=f"(v.y), "=f"(v.z), "=f"(v.w) : "l"(p));
    return v;
}
__device__ __forceinline__ uint2 ldcs2u(const void* p) {
    uint2 v;
    asm volatile("ld.global.cs.v2.u32 {%0,%1}, [%2];" : "=r"(v.x), "=r"(v.y) : "l"(p));
    return v;
}

// ============================================================
// prep: (blocks 0..63) dbc; (blocks 64..135) pack Wext fragments
// ============================================================
__device__ __forceinline__ float wval(const float* Wenc, const float* Watt,
                                      const float* convw, int h, int col) {
    if (col < ENC) return Wenc[(size_t)h * ENC + col];
    int cc = col - ENC;
    if (cc < KW) {
        float s = 0.f;
        #pragma unroll
        for (int c = 0; c < CONVC; c++) s += Watt[h * CONVC + c] * convw[c * KW + cc];
        return s;
    }
    return 0.f;
}

__global__ void prep_kernel(const float* __restrict__ dec_state,
                            const float* __restrict__ Wdec,
                            const float* __restrict__ benc,
                            const float* __restrict__ Wenc,
                            const float* __restrict__ Watt,
                            const float* __restrict__ convw) {
    if (blockIdx.x < Bb) {
        int b = blockIdx.x;
        int warp = threadIdx.x >> 5, lane = threadIdx.x & 31;
        for (int h = warp; h < HID; h += 8) {
            float s = 0.f;
            const float* xr = dec_state + (size_t)b * DEC;
            const float* wr = Wdec + (size_t)h * DEC;
            for (int c = lane * 4; c < DEC; c += 32 * 4) {
                float4 x = *(const float4*)&xr[c];
                float4 w = *(const float4*)&wr[c];
                s += x.x * w.x + x.y * w.y + x.z * w.z + x.w * w.w;
            }
            #pragma unroll
            for (int off = 16; off > 0; off >>= 1) s += __shfl_xor_sync(0xFFFFFFFFu, s, off);
            if (lane == 0) g_dbc[b * HID + h] = s + benc[h];
        }
    } else {
        int idx = (blockIdx.x - Bb) * 256 + threadIdx.x;
        if (idx >= KSTEPS * 512) return;
        int lane = idx & 31, pg = (idx >> 5) & 15, s = idx >> 9;
        int jj0 = (pg >> 2) * 8 + (pg & 3) * 2;
        int h0 = jj0 * 8 + (lane >> 2);
        int h1 = h0 + 8;
        int k = s * 16 + (lane & 3) * 2;
        uint4 r;
        r.x = packh(wval(Wenc, Watt, convw, h0, k),     wval(Wenc, Watt, convw, h0, k + 1));
        r.y = packh(wval(Wenc, Watt, convw, h0, k + 8), wval(Wenc, Watt, convw, h0, k + 9));
        r.z = packh(wval(Wenc, Watt, convw, h1, k),     wval(Wenc, Watt, convw, h1, k + 1));
        r.w = packh(wval(Wenc, Watt, convw, h1, k + 8), wval(Wenc, Watt, convw, h1, k + 9));
        g_Bp4[idx] = r;
    }
}

// ============================================================
// energy kernel: CTA = 64 t x 256 h; 8 warps (2 M x 4 N)
// K=64 fused steps: 8 full + 1 half (conv) -> 9 barriers
// Writes fp16 enc tiles to g_encH with streaming stores.
// ============================================================
#define ASTRIDE 72   // halves per row (144B) -> conflict-free ldmatrix
#define A_BUF_HALVES (64 * ASTRIDE)
#define DSMEM_A  (2 * A_BUF_HALVES * 2)        // 18432 B
#define DSMEM_SZ (DSMEM_A + 2 * 32768)         // + B stages = 83968 B

__global__ __launch_bounds__(256, 2)
void energy_kernel(const float* __restrict__ enc,
                   const float* __restrict__ prev,
                   const float* __restrict__ ww,
                   const float* __restrict__ wb) {
    extern __shared__ __align__(16) char dyn[];
    __half* aS = (__half*)dyn;                      // [2][64*ASTRIDE]
    const uint32_t bBase = smem_u32(dyn + DSMEM_A); // B stages: 2 x 32KB
    uint4* bS = (uint4*)(dyn + DSMEM_A);

    __shared__ float wwS[HID], dbS[HID];
    __shared__ float redS[64][5];

    const int tid = threadIdx.x;
    const int b = blockIdx.y, t0 = blockIdx.x * 64;
    const int warp = tid >> 5, lane = tid & 31;
    const int warp_m = warp >> 2, warp_n = warp & 3;
    const int g = lane >> 2, tq = lane & 3;

    if (tid < HID) {
        wwS[tid] = ww[tid];
        dbS[tid] = g_dbc[b * HID + tid];
    }

    float d[2][8][4];
    #pragma unroll
    for (int mi = 0; mi < 2; mi++)
        #pragma unroll
        for (int jj = 0; jj < 8; jj++)
            #pragma unroll
            for (int q = 0; q < 4; q++) d[mi][jj][q] = 0.f;

    const float* encB = enc + (size_t)b * Tt * ENC;
    const float* prevB = prev + b * Tt;

    // staging: row = tid>>2 (0..63), cols (tid&3)*16 .. +15
    const int srow = tid >> 2, sc0 = (tid & 3) * 16;
    __half* gHrow = g_encH + ((size_t)b * Tt + t0 + srow) * ENC + sc0;

    // ldmatrix base addresses: [buf][mi]; kh adds kh*32 bytes
    const int lm = lane >> 3, lr = lane & 7;
    const int arow0 = warp_m * 32 + (lm & 1) * 8 + lr;
    const int acol = (lm >> 1) * 8;
    const uint32_t la00 = smem_u32(&aS[(arow0 +  0) * ASTRIDE + acol]);
    const uint32_t la01 = smem_u32(&aS[(arow0 + 16) * ASTRIDE + acol]);
    const uint32_t la10 = la00 + A_BUF_HALVES * 2;
    const uint32_t la11 = la01 + A_BUF_HALVES * 2;

    // ---- prologue: B stage 0 (32KB); A step 0 in regs ----
    {
        uint32_t dst = bBase + tid * 16;
        #pragma unroll
        for (int q = 0; q < 8; q++)
            cp_async16(dst + q * 4096, &g_Bp4[q * 256 + tid]);
        CP_COMMIT();
    }
    float4 pA, pB, pC, pD;
    pA = ldcs4f((const float4*)&encB[(size_t)(t0 + srow) * ENC + sc0]);
    pB = ldcs4f((const float4*)&encB[(size_t)(t0 + srow) * ENC + sc0 + 4]);
    pC = ldcs4f((const float4*)&encB[(size_t)(t0 + srow) * ENC + sc0 + 8]);
    pD = ldcs4f((const float4*)&encB[(size_t)(t0 + srow) * ENC + sc0 + 12]);

    // PF: 0 = enc prefetch + full B, 2 = none (tail)
#define FSTEP(S, BUF, LM0, LM1, PF, NKH) do {                                     \
    {                                                                             \
        uint32_t sb_ = (BUF) * A_BUF_HALVES;                                      \
        uint4 u0, u1;                                                             \
        u0.x = packh(pA.x, pA.y); u0.y = packh(pA.z, pA.w);                       \
        u0.z = packh(pB.x, pB.y); u0.w = packh(pB.z, pB.w);                       \
        u1.x = packh(pC.x, pC.y); u1.y = packh(pC.z, pC.w);                       \
        u1.z = packh(pD.x, pD.y); u1.w = packh(pD.z, pD.w);                       \
        *(uint4*)&aS[sb_ + srow * ASTRIDE + sc0]     = u0;                        \
        *(uint4*)&aS[sb_ + srow * ASTRIDE + sc0 + 8] = u1;                        \
        if ((S) < 8) {                                                            \
            stcs4((uint4*)&gHrow[(S) * 64], u0);                                  \
            stcs4((uint4*)&gHrow[(S) * 64 + 8], u1);                              \
        }                                                                         \
    }                                                                             \
    CP_WAIT0();                                                                   \
    __syncthreads();                                                              \
    if (PF == 0) {                                                                \
        const int _sn = (S) + 1;                                                  \
        uint32_t _bd = bBase + ((_sn) & 1) * 32768 + tid * 16;                    \
        const int _nq = (_sn < 8) ? 8 : 4;                                        \
        for (int q = 0; q < _nq; q++)                                             \
            cp_async16(_bd + q * 4096, &g_Bp4[_sn * 2048 + q * 256 + tid]);       \
        CP_COMMIT();                                                              \
        if (_sn < 8) {                                                            \
            const float* _r = &encB[(size_t)(t0 + srow) * ENC + _sn * 64 + sc0];  \
            pA = ldcs4f((const float4*)&_r[0]);  pB = ldcs4f((const float4*)&_r[4]); \
            pC = ldcs4f((const float4*)&_r[8]);  pD = ldcs4f((const float4*)&_r[12]);\
        } else {                                                                  \
            float _v[16];                                                         \
            _Pragma("unroll")                                                     \
            for (int i = 0; i < 16; i++) {                                        \
                int cc = sc0 + i;                                                 \
                float x = 0.f;                                                    \
                if (cc < KW) {                                                    \
                    int src = t0 + srow + cc - PADW;                              \
                    if (src >= 0 && src < Tt) x = prevB[src];                     \
                }                                                                 \
                _v[i] = x;                                                        \
            }                                                                     \
            pA.x=_v[0]; pA.y=_v[1]; pA.z=_v[2]; pA.w=_v[3];                       \
            pB.x=_v[4]; pB.y=_v[5]; pB.z=_v[6]; pB.w=_v[7];                       \
            pC.x=_v[8]; pC.y=_v[9]; pC.z=_v[10]; pC.w=_v[11];                     \
            pD.x=_v[12]; pD.y=_v[13]; pD.z=_v[14]; pD.w=_v[15];                   \
        }                                                                         \
    }                                                                             \
    _Pragma("unroll")                                                             \
    for (int kh = 0; kh < (NKH); kh++) {                                          \
        uint32_t a0[4], a1[4];                                                    \
        LDMAT(a0, (LM0) + kh * 32);                                               \
        LDMAT(a1, (LM1) + kh * 32);                                               \
        _Pragma("unroll")                                                         \
        for (int p = 0; p < 4; p++) {                                             \
            uint4 B2 = bS[(BUF) * 2048 + kh * 512 + (warp_n * 4 + p) * 32 + lane];\
            mma16816(d[0][p * 2 + 0], a0, B2.x, B2.y);                            \
            mma16816(d[0][p * 2 + 1], a0, B2.z, B2.w);                            \
            mma16816(d[1][p * 2 + 0], a1, B2.x, B2.y);                            \
            mma16816(d[1][p * 2 + 1], a1, B2.z, B2.w);                            \
        }                                                                         \
    }                                                                             \
} while (0)

    for (int s = 0; s < 8; s += 2) {
        FSTEP(s,     0, la00, la01, 0, 4);
        FSTEP(s + 1, 1, la10, la11, 0, 4);
    }
    FSTEP(8, 0, la00, la01, 2, 2);   // conv tail: K=32
#undef FSTEP

    // ---- epilogue: e(row) = sum_h ww[h]*tanh(C + dbc[h]) ----
    float ww0[8], ww1[8], db0[8], db1[8];
    #pragma unroll
    for (int jj = 0; jj < 8; jj++) {
        int h = warp_n * 64 + jj * 8 + tq * 2;
        ww0[jj] = wwS[h];     ww1[jj] = wwS[h + 1];
        db0[jj] = dbS[h];     db1[jj] = dbS[h + 1];
    }
    #pragma unroll
    for (int mi = 0; mi < 2; mi++) {
        #pragma unroll
        for (int half = 0; half < 2; half++) {
            float e = 0.f;
            #pragma unroll
            for (int jj = 0; jj < 8; jj++) {
                e += ww0[jj] * tanhf(d[mi][jj][half * 2 + 0] + db0[jj]);
                e += ww1[jj] * tanhf(d[mi][jj][half * 2 + 1] + db1[jj]);
            }
            e += __shfl_xor_sync(0xFFFFFFFFu, e, 1);
            e += __shfl_xor_sync(0xFFFFFFFFu, e, 2);
            if (tq == 0)
                redS[warp_m * 32 + mi * 16 + half * 8 + g][warp_n] = e;
        }
    }
    __syncthreads();
    if (tid < 64) {
        float e = redS[tid][0] + redS[tid][1] + redS[tid][2] + redS[tid][3];
        g_energy[b * Tt + t0 + tid] = e + wb[0];
    }
}

// ============================================================
// softmax stats: per-b masked max + 1/sum
// ============================================================
__global__ void softmax_stats_kernel(const int* __restrict__ text_len) {
    const int b = blockIdx.x;
    const int tid = threadIdx.x;  // 512
    const int len = text_len[b];
    __shared__ float sh[512];

    float m = -3.402823466e+38f;
    for (int t = tid; t < Tt; t += 512)
        if (t < len) m = fmaxf(m, g_energy[b * Tt + t]);
    sh[tid] = m; __syncthreads();
    for (int s = 256; s > 0; s >>= 1) {
        if (tid < s) sh[tid] = fmaxf(sh[tid], sh[tid + s]);
        __syncthreads();
    }
    const float M = sh[0];
    __syncthreads();

    float sum = 0.f;
    for (int t = tid; t < Tt; t += 512)
        if (t < len) sum += __expf(g_energy[b * Tt + t] - M);
    sh[tid] = sum; __syncthreads();
    for (int s = 256; s > 0; s >>= 1) {
        if (tid < s) sh[tid] += sh[tid + s];
        __syncthreads();
    }
    if (tid == 0) {
        g_stat[2 * b]     = M;
        g_stat[2 * b + 1] = 1.f / sh[0];
    }
}

// ============================================================
// att_c partials from fp16 enc cache (streaming loads); writes att_w
// ============================================================
__global__ void attc_part_kernel(const int* __restrict__ text_len,
                                 float* __restrict__ out_w) {
    const int b = blockIdx.y, seg = blockIdx.x;
    const int c4 = threadIdx.x;  // 128 threads, 4 cols each
    const int tstart = seg * (Tt / NSEG);
    __shared__ float wS[Tt / NSEG];

    if (c4 < Tt / NSEG) {
        const int t = tstart + c4;
        const int len = text_len[b];
        const float M = g_stat[2 * b], invS = g_stat[2 * b + 1];
        float w = (t < len) ? __expf(g_energy[b * Tt + t] - M) * invS : 0.f;
        wS[c4] = w;
        out_w[b * Tt + t] = w;
    }
    __syncthreads();

    float4 s = {0.f, 0.f, 0.f, 0.f};
    const __half* eh = g_encH + ((size_t)b * Tt + tstart) * ENC + c4 * 4;
    #pragma unroll 4
    for (int i = 0; i < Tt / NSEG; i++) {
        float w = wS[i];
        uint2 u = ldcs2u(eh + (size_t)i * ENC);
        float2 v0 = __half22float2(*(__half2*)&u.x);
        float2 v1 = __half22float2(*(__half2*)&u.y);
        s.x = fmaf(v0.x, w, s.x);
        s.y = fmaf(v0.y, w, s.y);
        s.z = fmaf(v1.x, w, s.z);
        s.w = fmaf(v1.y, w, s.w);
    }
    *(float4*)&g_part[(seg * Bb + b) * ENC + c4 * 4] = s;
}

__global__ void attc_reduce_kernel(float* __restrict__ out_c) {
    const int b = blockIdx.x;
    const int c = threadIdx.x;  // 512
    float s = 0.f;
    #pragma unroll
    for (int seg = 0; seg < NSEG; seg++)
        s += g_part[(seg * Bb + b) * ENC + c];
    out_c[b * ENC + c] = s;
}

// ============================================================
extern "C" void kernel_launch(void* const* d_in, const int* in_sizes, int n_in,
                              void* d_out, int out_size) {
    const float* enc       = (const float*)d_in[0];   // (B,T,ENC)
    const float* dec_state = (const float*)d_in[1];   // (B,DEC)
    const float* prev      = (const float*)d_in[2];   // (B,T)
    const int*   text_len  = (const int*)  d_in[3];   // (B,)
    const float* Wenc      = (const float*)d_in[4];   // (HID,ENC)
    const float* benc      = (const float*)d_in[5];   // (HID,)
    const float* Wdec      = (const float*)d_in[6];   // (HID,DEC)
    const float* Watt      = (const float*)d_in[7];   // (HID,CONV)
    const float* convw     = (const float*)d_in[8];   // (CONV,1,K)
    const float* ww        = (const float*)d_in[9];   // (1,HID)
    const float* wb        = (const float*)d_in[10];  // (1,)

    float* out   = (float*)d_out;
    float* out_c = out;                 // att_c: (B,ENC)
    float* out_w = out + Bb * ENC;      // att_w: (B,T)

    cudaFuncSetAttribute(energy_kernel, cudaFuncAttributeMaxDynamicSharedMemorySize, DSMEM_SZ);

    prep_kernel<<<Bb + (KSTEPS * 512 + 255) / 256, 256>>>(dec_state, Wdec, benc,
                                                          Wenc, Watt, convw);
    energy_kernel<<<dim3(Tt / 64, Bb), 256, DSMEM_SZ>>>(enc, prev, ww, wb);
    softmax_stats_kernel<<<Bb, 512>>>(text_len);
    attc_part_kernel<<<dim3(NSEG, Bb), 128>>>(text_len, out_w);
    attc_reduce_kernel<<<Bb, ENC>>>(out_c);
}

// round 17
// speedup vs baseline: 1.3167x; 1.1943x over previous
#include <cuda_runtime.h>
#include <cuda_fp16.h>
#include <math.h>
#include <stdint.h>

#define Bb    64
#define Tt    2048
#define ENC   512
#define DEC   1024
#define CONVC 32
#define KW    31
#define HID   256
#define PADW  15

#define KSTEPS 36             // 16-col sub-steps in packed B (incl. zero pad)
#define NSEG   32

// ---------------- device scratch ----------------
__device__ float  g_dbc[Bb * HID];                // dec@Wdec^T + b_enc
__device__ uint4  g_Bp4[KSTEPS * 512];            // fp16 weights, paired n8 tiles
__device__ float  g_energy[Bb * Tt];
__device__ float  g_part[NSEG * Bb * ENC];
__device__ float  g_stat[2 * Bb];                 // {M, 1/sum} per batch
__device__ __half g_encH[(size_t)Bb * Tt * ENC];  // fp16 enc cache (128 MiB)

// ---------------- helpers ----------------
__device__ __forceinline__ uint32_t packh(float x, float y) {
    __half2 h = __floats2half2_rn(x, y);
    return *(uint32_t*)&h;
}
__device__ __forceinline__ uint32_t smem_u32(const void* p) {
    uint32_t a;
    asm("{ .reg .u64 t; cvta.to.shared.u64 t, %1; cvt.u32.u64 %0, t; }" : "=r"(a) : "l"(p));
    return a;
}
__device__ __forceinline__ void mma16816(float* d, const uint32_t* a,
                                         uint32_t b0, uint32_t b1) {
    asm volatile(
        "mma.sync.aligned.m16n8k16.row.col.f32.f16.f16.f32 "
        "{%0,%1,%2,%3}, {%4,%5,%6,%7}, {%8,%9}, {%0,%1,%2,%3};"
        : "+f"(d[0]), "+f"(d[1]), "+f"(d[2]), "+f"(d[3])
        : "r"(a[0]), "r"(a[1]), "r"(a[2]), "r"(a[3]), "r"(b0), "r"(b1));
}
__device__ __forceinline__ void cp_async16(uint32_t dst, const void* src) {
    asm volatile("cp.async.ca.shared.global [%0], [%1], 16;" :: "r"(dst), "l"(src));
}
#define CP_COMMIT() asm volatile("cp.async.commit_group;" ::: "memory")
#define CP_WAIT0()  asm volatile("cp.async.wait_group 0;" ::: "memory")
#define LDMAT(r, ad)                                                              \
    asm volatile("ldmatrix.sync.aligned.m8n8.x4.shared.b16 {%0,%1,%2,%3}, [%4];"  \
        : "=r"((r)[0]), "=r"((r)[1]), "=r"((r)[2]), "=r"((r)[3]) : "r"(ad))

// streaming (evict-first) global accessors
__device__ __forceinline__ void stcs4(uint4* p, uint4 v) {
    asm volatile("st.global.cs.v4.u32 [%0], {%1,%2,%3,%4};"
                 :: "l"(p), "r"(v.x), "r"(v.y), "r"(v.z), "r"(v.w) : "memory");
}
__device__ __forceinline__ float4 ldcs4f(const float4* p) {
    float4 v;
    asm volatile("ld.global.cs.v4.f32 {%0,%1,%2,%3}, [%4];"
                 : "=f"(v.x), "=f"(v.y), "=f"(v.z), "=f"(v.w) : "l"(p));
    return v;
}
__device__ __forceinline__ uint2 ldcs2u(const void* p) {
    uint2 v;
    asm volatile("ld.global.cs.v2.u32 {%0,%1}, [%2];" : "=r"(v.x), "=r"(v.y) : "l"(p));
    return v;
}

// ============================================================
// prep: (blocks 0..63) dbc; (blocks 64..135) pack Wext fragments
// ============================================================
__device__ __forceinline__ float wval(const float* Wenc, const float* Watt,
                                      const float* convw, int h, int col) {
    if (col < ENC) return Wenc[(size_t)h * ENC + col];
    int cc = col - ENC;
    if (cc < KW) {
        float s = 0.f;
        #pragma unroll
        for (int c = 0; c < CONVC; c++) s += Watt[h * CONVC + c] * convw[c * KW + cc];
        return s;
    }
    return 0.f;
}

__global__ void prep_kernel(const float* __restrict__ dec_state,
                            const float* __restrict__ Wdec,
                            const float* __restrict__ benc,
                            const float* __restrict__ Wenc,
                            const float* __restrict__ Watt,
                            const float* __restrict__ convw) {
    if (blockIdx.x < Bb) {
        int b = blockIdx.x;
        int warp = threadIdx.x >> 5, lane = threadIdx.x & 31;
        for (int h = warp; h < HID; h += 8) {
            float s = 0.f;
            const float* xr = dec_state + (size_t)b * DEC;
            const float* wr = Wdec + (size_t)h * DEC;
            for (int c = lane * 4; c < DEC; c += 32 * 4) {
                float4 x = *(const float4*)&xr[c];
                float4 w = *(const float4*)&wr[c];
                s += x.x * w.x + x.y * w.y + x.z * w.z + x.w * w.w;
            }
            #pragma unroll
            for (int off = 16; off > 0; off >>= 1) s += __shfl_xor_sync(0xFFFFFFFFu, s, off);
            if (lane == 0) g_dbc[b * HID + h] = s + benc[h];
        }
    } else {
        int idx = (blockIdx.x - Bb) * 256 + threadIdx.x;
        if (idx >= KSTEPS * 512) return;
        int lane = idx & 31, pg = (idx >> 5) & 15, s = idx >> 9;
        int jj0 = (pg >> 2) * 8 + (pg & 3) * 2;
        int h0 = jj0 * 8 + (lane >> 2);
        int h1 = h0 + 8;
        int k = s * 16 + (lane & 3) * 2;
        uint4 r;
        r.x = packh(wval(Wenc, Watt, convw, h0, k),     wval(Wenc, Watt, convw, h0, k + 1));
        r.y = packh(wval(Wenc, Watt, convw, h0, k + 8), wval(Wenc, Watt, convw, h0, k + 9));
        r.z = packh(wval(Wenc, Watt, convw, h1, k),     wval(Wenc, Watt, convw, h1, k + 1));
        r.w = packh(wval(Wenc, Watt, convw, h1, k + 8), wval(Wenc, Watt, convw, h1, k + 9));
        g_Bp4[idx] = r;
    }
}

// ============================================================
// energy kernel: CTA = 64 t x 256 h; 8 warps (2 M x 4 N)
// K=64 fused steps: 8 full + 1 half (conv) -> 9 barriers
// Early-exits masked t-tiles (t0 >= text_len[b]).
// ============================================================
#define ASTRIDE 72   // halves per row (144B) -> conflict-free ldmatrix
#define A_BUF_HALVES (64 * ASTRIDE)
#define DSMEM_A  (2 * A_BUF_HALVES * 2)        // 18432 B
#define DSMEM_SZ (DSMEM_A + 2 * 32768)         // + B stages = 83968 B

__global__ __launch_bounds__(256, 2)
void energy_kernel(const float* __restrict__ enc,
                   const float* __restrict__ prev,
                   const float* __restrict__ ww,
                   const float* __restrict__ wb,
                   const int* __restrict__ text_len) {
    const int b = blockIdx.y, t0 = blockIdx.x * 64;
    if (t0 >= text_len[b]) return;   // masked tile: outputs never read

    extern __shared__ __align__(16) char dyn[];
    __half* aS = (__half*)dyn;                      // [2][64*ASTRIDE]
    const uint32_t bBase = smem_u32(dyn + DSMEM_A); // B stages: 2 x 32KB
    uint4* bS = (uint4*)(dyn + DSMEM_A);

    __shared__ float wwS[HID], dbS[HID];
    __shared__ float redS[64][5];

    const int tid = threadIdx.x;
    const int warp = tid >> 5, lane = tid & 31;
    const int warp_m = warp >> 2, warp_n = warp & 3;
    const int g = lane >> 2, tq = lane & 3;

    if (tid < HID) {
        wwS[tid] = ww[tid];
        dbS[tid] = g_dbc[b * HID + tid];
    }

    float d[2][8][4];
    #pragma unroll
    for (int mi = 0; mi < 2; mi++)
        #pragma unroll
        for (int jj = 0; jj < 8; jj++)
            #pragma unroll
            for (int q = 0; q < 4; q++) d[mi][jj][q] = 0.f;

    const float* encB = enc + (size_t)b * Tt * ENC;
    const float* prevB = prev + b * Tt;

    // staging: row = tid>>2 (0..63), cols (tid&3)*16 .. +15
    const int srow = tid >> 2, sc0 = (tid & 3) * 16;
    __half* gHrow = g_encH + ((size_t)b * Tt + t0 + srow) * ENC + sc0;

    // ldmatrix base addresses: [buf][mi]; kh adds kh*32 bytes
    const int lm = lane >> 3, lr = lane & 7;
    const int arow0 = warp_m * 32 + (lm & 1) * 8 + lr;
    const int acol = (lm >> 1) * 8;
    const uint32_t la00 = smem_u32(&aS[(arow0 +  0) * ASTRIDE + acol]);
    const uint32_t la01 = smem_u32(&aS[(arow0 + 16) * ASTRIDE + acol]);
    const uint32_t la10 = la00 + A_BUF_HALVES * 2;
    const uint32_t la11 = la01 + A_BUF_HALVES * 2;

    // ---- prologue: B stage 0 (32KB); A step 0 in regs ----
    {
        uint32_t dst = bBase + tid * 16;
        #pragma unroll
        for (int q = 0; q < 8; q++)
            cp_async16(dst + q * 4096, &g_Bp4[q * 256 + tid]);
        CP_COMMIT();
    }
    float4 pA, pB, pC, pD;
    pA = ldcs4f((const float4*)&encB[(size_t)(t0 + srow) * ENC + sc0]);
    pB = ldcs4f((const float4*)&encB[(size_t)(t0 + srow) * ENC + sc0 + 4]);
    pC = ldcs4f((const float4*)&encB[(size_t)(t0 + srow) * ENC + sc0 + 8]);
    pD = ldcs4f((const float4*)&encB[(size_t)(t0 + srow) * ENC + sc0 + 12]);

    // PF: 0 = enc prefetch + full B, 2 = none (tail)
#define FSTEP(S, BUF, LM0, LM1, PF, NKH) do {                                     \
    {                                                                             \
        uint32_t sb_ = (BUF) * A_BUF_HALVES;                                      \
        uint4 u0, u1;                                                             \
        u0.x = packh(pA.x, pA.y); u0.y = packh(pA.z, pA.w);                       \
        u0.z = packh(pB.x, pB.y); u0.w = packh(pB.z, pB.w);                       \
        u1.x = packh(pC.x, pC.y); u1.y = packh(pC.z, pC.w);                       \
        u1.z = packh(pD.x, pD.y); u1.w = packh(pD.z, pD.w);                       \
        *(uint4*)&aS[sb_ + srow * ASTRIDE + sc0]     = u0;                        \
        *(uint4*)&aS[sb_ + srow * ASTRIDE + sc0 + 8] = u1;                        \
        if ((S) < 8) {                                                            \
            stcs4((uint4*)&gHrow[(S) * 64], u0);                                  \
            stcs4((uint4*)&gHrow[(S) * 64 + 8], u1);                              \
        }                                                                         \
    }                                                                             \
    CP_WAIT0();                                                                   \
    __syncthreads();                                                              \
    if (PF == 0) {                                                                \
        const int _sn = (S) + 1;                                                  \
        uint32_t _bd = bBase + ((_sn) & 1) * 32768 + tid * 16;                    \
        const int _nq = (_sn < 8) ? 8 : 4;                                        \
        for (int q = 0; q < _nq; q++)                                             \
            cp_async16(_bd + q * 4096, &g_Bp4[_sn * 2048 + q * 256 + tid]);       \
        CP_COMMIT();                                                              \
        if (_sn < 8) {                                                            \
            const float* _r = &encB[(size_t)(t0 + srow) * ENC + _sn * 64 + sc0];  \
            pA = ldcs4f((const float4*)&_r[0]);  pB = ldcs4f((const float4*)&_r[4]); \
            pC = ldcs4f((const float4*)&_r[8]);  pD = ldcs4f((const float4*)&_r[12]);\
        } else {                                                                  \
            float _v[16];                                                         \
            _Pragma("unroll")                                                     \
            for (int i = 0; i < 16; i++) {                                        \
                int cc = sc0 + i;                                                 \
                float x = 0.f;                                                    \
                if (cc < KW) {                                                    \
                    int src = t0 + srow + cc - PADW;                              \
                    if (src >= 0 && src < Tt) x = prevB[src];                     \
                }                                                                 \
                _v[i] = x;                                                        \
            }                                                                     \
            pA.x=_v[0]; pA.y=_v[1]; pA.z=_v[2]; pA.w=_v[3];                       \
            pB.x=_v[4]; pB.y=_v[5]; pB.z=_v[6]; pB.w=_v[7];                       \
            pC.x=_v[8]; pC.y=_v[9]; pC.z=_v[10]; pC.w=_v[11];                     \
            pD.x=_v[12]; pD.y=_v[13]; pD.z=_v[14]; pD.w=_v[15];                   \
        }                                                                         \
    }                                                                             \
    _Pragma("unroll")                                                             \
    for (int kh = 0; kh < (NKH); kh++) {                                          \
        uint32_t a0[4], a1[4];                                                    \
        LDMAT(a0, (LM0) + kh * 32);                                               \
        LDMAT(a1, (LM1) + kh * 32);                                               \
        _Pragma("unroll")                                                         \
        for (int p = 0; p < 4; p++) {                                             \
            uint4 B2 = bS[(BUF) * 2048 + kh * 512 + (warp_n * 4 + p) * 32 + lane];\
            mma16816(d[0][p * 2 + 0], a0, B2.x, B2.y);                            \
            mma16816(d[0][p * 2 + 1], a0, B2.z, B2.w);                            \
            mma16816(d[1][p * 2 + 0], a1, B2.x, B2.y);                            \
            mma16816(d[1][p * 2 + 1], a1, B2.z, B2.w);                            \
        }                                                                         \
    }                                                                             \
} while (0)

    for (int s = 0; s < 8; s += 2) {
        FSTEP(s,     0, la00, la01, 0, 4);
        FSTEP(s + 1, 1, la10, la11, 0, 4);
    }
    FSTEP(8, 0, la00, la01, 2, 2);   // conv tail: K=32
#undef FSTEP

    // ---- epilogue: e(row) = sum_h ww[h]*tanh(C + dbc[h]) ----
    float ww0[8], ww1[8], db0[8], db1[8];
    #pragma unroll
    for (int jj = 0; jj < 8; jj++) {
        int h = warp_n * 64 + jj * 8 + tq * 2;
        ww0[jj] = wwS[h];     ww1[jj] = wwS[h + 1];
        db0[jj] = dbS[h];     db1[jj] = dbS[h + 1];
    }
    #pragma unroll
    for (int mi = 0; mi < 2; mi++) {
        #pragma unroll
        for (int half = 0; half < 2; half++) {
            float e = 0.f;
            #pragma unroll
            for (int jj = 0; jj < 8; jj++) {
                e += ww0[jj] * tanhf(d[mi][jj][half * 2 + 0] + db0[jj]);
                e += ww1[jj] * tanhf(d[mi][jj][half * 2 + 1] + db1[jj]);
            }
            e += __shfl_xor_sync(0xFFFFFFFFu, e, 1);
            e += __shfl_xor_sync(0xFFFFFFFFu, e, 2);
            if (tq == 0)
                redS[warp_m * 32 + mi * 16 + half * 8 + g][warp_n] = e;
        }
    }
    __syncthreads();
    if (tid < 64) {
        float e = redS[tid][0] + redS[tid][1] + redS[tid][2] + redS[tid][3];
        g_energy[b * Tt + t0 + tid] = e + wb[0];
    }
}

// ============================================================
// softmax stats: per-b masked max + 1/sum
// ============================================================
__global__ void softmax_stats_kernel(const int* __restrict__ text_len) {
    const int b = blockIdx.x;
    const int tid = threadIdx.x;  // 512
    const int len = text_len[b];
    __shared__ float sh[512];

    float m = -3.402823466e+38f;
    for (int t = tid; t < Tt; t += 512)
        if (t < len) m = fmaxf(m, g_energy[b * Tt + t]);
    sh[tid] = m; __syncthreads();
    for (int s = 256; s > 0; s >>= 1) {
        if (tid < s) sh[tid] = fmaxf(sh[tid], sh[tid + s]);
        __syncthreads();
    }
    const float M = sh[0];
    __syncthreads();

    float sum = 0.f;
    for (int t = tid; t < Tt; t += 512)
        if (t < len) sum += __expf(g_energy[b * Tt + t] - M);
    sh[tid] = sum; __syncthreads();
    for (int s = 256; s > 0; s >>= 1) {
        if (tid < s) sh[tid] += sh[tid + s];
        __syncthreads();
    }
    if (tid == 0) {
        g_stat[2 * b]     = M;
        g_stat[2 * b + 1] = 1.f / sh[0];
    }
}

// ============================================================
// att_c partials from fp16 enc cache (streaming); writes att_w
// Early-exits fully-masked segments.
// ============================================================
__global__ void attc_part_kernel(const int* __restrict__ text_len,
                                 float* __restrict__ out_w) {
    const int b = blockIdx.y, seg = blockIdx.x;
    const int c4 = threadIdx.x;  // 128 threads, 4 cols each
    const int tstart = seg * (Tt / NSEG);
    const int len = text_len[b];
    __shared__ float wS[Tt / NSEG];

    if (tstart >= len) {   // fully masked: zero outputs, no enc traffic
        if (c4 < Tt / NSEG) out_w[b * Tt + tstart + c4] = 0.f;
        float4 z = {0.f, 0.f, 0.f, 0.f};
        *(float4*)&g_part[(seg * Bb + b) * ENC + c4 * 4] = z;
        return;
    }

    if (c4 < Tt / NSEG) {
        const int t = tstart + c4;
        const float M = g_stat[2 * b], invS = g_stat[2 * b + 1];
        float w = (t < len) ? __expf(g_energy[b * Tt + t] - M) * invS : 0.f;
        wS[c4] = w;
        out_w[b * Tt + t] = w;
    }
    __syncthreads();

    float4 s = {0.f, 0.f, 0.f, 0.f};
    const __half* eh = g_encH + ((size_t)b * Tt + tstart) * ENC + c4 * 4;
    #pragma unroll 4
    for (int i = 0; i < Tt / NSEG; i++) {
        float w = wS[i];
        uint2 u = ldcs2u(eh + (size_t)i * ENC);
        float2 v0 = __half22float2(*(__half2*)&u.x);
        float2 v1 = __half22float2(*(__half2*)&u.y);
        s.x = fmaf(v0.x, w, s.x);
        s.y = fmaf(v0.y, w, s.y);
        s.z = fmaf(v1.x, w, s.z);
        s.w = fmaf(v1.y, w, s.w);
    }
    *(float4*)&g_part[(seg * Bb + b) * ENC + c4 * 4] = s;
}

__global__ void attc_reduce_kernel(float* __restrict__ out_c) {
    const int b = blockIdx.x;
    const int c = threadIdx.x;  // 512
    float s = 0.f;
    #pragma unroll
    for (int seg = 0; seg < NSEG; seg++)
        s += g_part[(seg * Bb + b) * ENC + c];
    out_c[b * ENC + c] = s;
}

// ============================================================
extern "C" void kernel_launch(void* const* d_in, const int* in_sizes, int n_in,
                              void* d_out, int out_size) {
    const float* enc       = (const float*)d_in[0];   // (B,T,ENC)
    const float* dec_state = (const float*)d_in[1];   // (B,DEC)
    const float* prev      = (const float*)d_in[2];   // (B,T)
    const int*   text_len  = (const int*)  d_in[3];   // (B,)
    const float* Wenc      = (const float*)d_in[4];   // (HID,ENC)
    const float* benc      = (const float*)d_in[5];   // (HID,)
    const float* Wdec      = (const float*)d_in[6];   // (HID,DEC)
    const float* Watt      = (const float*)d_in[7];   // (HID,CONV)
    const float* convw     = (const float*)d_in[8];   // (CONV,1,K)
    const float* ww        = (const float*)d_in[9];   // (1,HID)
    const float* wb        = (const float*)d_in[10];  // (1,)

    float* out   = (float*)d_out;
    float* out_c = out;                 // att_c: (B,ENC)
    float* out_w = out + Bb * ENC;      // att_w: (B,T)

    cudaFuncSetAttribute(energy_kernel, cudaFuncAttributeMaxDynamicSharedMemorySize, DSMEM_SZ);

    prep_kernel<<<Bb + (KSTEPS * 512 + 255) / 256, 256>>>(dec_state, Wdec, benc,
                                                          Wenc, Watt, convw);
    energy_kernel<<<dim3(Tt / 64, Bb), 256, DSMEM_SZ>>>(enc, prev, ww, wb, text_len);
    softmax_stats_kernel<<<Bb, 512>>>(text_len);
    attc_part_kernel<<<dim3(NSEG, Bb), 128>>>(text_len, out_w);
    attc_reduce_kernel<<<Bb, ENC>>>(out_c);
}